// round 3
// baseline (speedup 1.0000x reference)
#include <cuda_runtime.h>
#include <cstdint>

#define NN 100000
#define EE 1600000
#define F1 512
#define F3 128
#define H  128
#define C  64
#define SW 0.2f
#define FW 0.8f
#define BN_EPS 1e-5f

// ---- scratch (device globals; no allocation allowed) ----
__device__ float g_Wc1[F1 * H];   // FW * W1 @ Wg1
__device__ float g_Wc2[F3 * H];   // SW * W2 @ Wg1
__device__ float g_bz[H];         // (FW*b1 + SW*b2) @ Wg1
__device__ float g_s[H];          // gamma * rsqrt(var+eps)
__device__ float g_t[H];          // (bg1 - mean)*s + beta
__device__ float g_z[(size_t)NN * H];    // 51.2 MB
__device__ float g_agg[(size_t)NN * H];  // 51.2 MB
__device__ float g_z2[(size_t)NN * C];   // 25.6 MB

// ============================================================
// Prolog: combine weights + BN affine. 641 blocks x 128 threads.
// ============================================================
__global__ void prep_kernel(const float* __restrict__ W1, const float* __restrict__ b1,
                            const float* __restrict__ W2, const float* __restrict__ b2,
                            const float* __restrict__ Wg1, const float* __restrict__ bg1,
                            const float* __restrict__ gamma, const float* __restrict__ beta,
                            const float* __restrict__ rmean, const float* __restrict__ rvar) {
    int j = threadIdx.x;      // 0..127 (output column)
    int b = blockIdx.x;
    __shared__ float a[H];
    if (b < F1) {
        a[j] = W1[b * H + j];
        __syncthreads();
        float acc = 0.f;
        #pragma unroll 8
        for (int k = 0; k < H; k++) acc += a[k] * Wg1[k * H + j];
        g_Wc1[b * H + j] = FW * acc;
    } else if (b < F1 + F3) {
        int r = b - F1;
        a[j] = W2[r * H + j];
        __syncthreads();
        float acc = 0.f;
        #pragma unroll 8
        for (int k = 0; k < H; k++) acc += a[k] * Wg1[k * H + j];
        g_Wc2[r * H + j] = SW * acc;
    } else {
        a[j] = FW * b1[j] + SW * b2[j];
        __syncthreads();
        float acc = 0.f;
        #pragma unroll 8
        for (int k = 0; k < H; k++) acc += a[k] * Wg1[k * H + j];
        g_bz[j] = acc;
        float sc = gamma[j] * rsqrtf(rvar[j] + BN_EPS);
        g_s[j] = sc;
        g_t[j] = (bg1[j] - rmean[j]) * sc + beta[j];
    }
}

// ============================================================
// Init: zero g_agg, set out[n][c] = bg2[c]. float4 granularity.
// ============================================================
__global__ void init_kernel(const float* __restrict__ bg2, float* __restrict__ out) {
    const long long AGG4 = (long long)NN * H / 4;
    const long long OUT4 = (long long)NN * C / 4;
    long long i = (long long)blockIdx.x * blockDim.x + threadIdx.x;
    if (i < AGG4) {
        reinterpret_cast<float4*>(g_agg)[i] = make_float4(0.f, 0.f, 0.f, 0.f);
    } else {
        long long o = i - AGG4;
        if (o < OUT4) {
            float4 v = reinterpret_cast<const float4*>(bg2)[o & (C / 4 - 1)];
            reinterpret_cast<float4*>(out)[o] = v;
        }
    }
}

// ============================================================
// GEMM1: g_z[N,128] = x1 @ Wc1 + x2 @ Wc2 + bz
// Block: 64 rows x 128 cols. 256 threads; thread = 8x4 outputs.
// ============================================================
__global__ __launch_bounds__(256) void gemm1_kernel(const float* __restrict__ x1,
                                                    const float* __restrict__ x2) {
    __shared__ float As[16][64];
    __shared__ float Bs[16][128];

    const int tid = threadIdx.x;
    const int tx = tid & 31;   // col group: cols tx*4..tx*4+3
    const int ty = tid >> 5;   // row group: rows ty*8..ty*8+7
    const int row0 = blockIdx.x * 64;

    float acc[8][4];
    {
        float4 bz = reinterpret_cast<const float4*>(g_bz)[tx];
        #pragma unroll
        for (int i = 0; i < 8; i++) {
            acc[i][0] = bz.x; acc[i][1] = bz.y; acc[i][2] = bz.z; acc[i][3] = bz.w;
        }
    }

    #pragma unroll
    for (int phase = 0; phase < 2; phase++) {
        const float* __restrict__ X = phase ? x2 : x1;
        const float* __restrict__ W = phase ? g_Wc2 : g_Wc1;
        const int K = phase ? F3 : F1;

        for (int kb = 0; kb < K; kb += 16) {
            // A tile: 64 rows x 16 k  (one float4 per thread, store transposed)
            {
                int r  = tid >> 2;
                int kq = (tid & 3) << 2;
                int gr = row0 + r; if (gr >= NN) gr = NN - 1;
                float4 av = *reinterpret_cast<const float4*>(X + (size_t)gr * K + kb + kq);
                As[kq + 0][r] = av.x; As[kq + 1][r] = av.y;
                As[kq + 2][r] = av.z; As[kq + 3][r] = av.w;
            }
            // B tile: 16 k x 128 cols (two float4 per thread)
            {
                #pragma unroll
                for (int t = 0; t < 2; t++) {
                    int f  = tid + t * 256;
                    int k  = f >> 5;
                    int c4 = (f & 31) << 2;
                    float4 bv = *reinterpret_cast<const float4*>(W + (size_t)(kb + k) * H + c4);
                    *reinterpret_cast<float4*>(&Bs[k][c4]) = bv;
                }
            }
            __syncthreads();
            #pragma unroll
            for (int k = 0; k < 16; k++) {
                float4 a0 = *reinterpret_cast<const float4*>(&As[k][ty * 8]);
                float4 a1 = *reinterpret_cast<const float4*>(&As[k][ty * 8 + 4]);
                float4 bv = *reinterpret_cast<const float4*>(&Bs[k][tx * 4]);
                float ar[8] = {a0.x, a0.y, a0.z, a0.w, a1.x, a1.y, a1.z, a1.w};
                float br[4] = {bv.x, bv.y, bv.z, bv.w};
                #pragma unroll
                for (int i = 0; i < 8; i++)
                    #pragma unroll
                    for (int j = 0; j < 4; j++)
                        acc[i][j] += ar[i] * br[j];
            }
            __syncthreads();
        }
    }

    #pragma unroll
    for (int i = 0; i < 8; i++) {
        int gr = row0 + ty * 8 + i;
        if (gr < NN) {
            float4 v = make_float4(acc[i][0], acc[i][1], acc[i][2], acc[i][3]);
            *reinterpret_cast<float4*>(g_z + (size_t)gr * H + tx * 4) = v;
        }
    }
}

// ============================================================
// Scatter1: agg[dst] += z[src].  One warp per edge; lane handles float4.
// edge_index is INT32 (jax x64-disabled downcasts int64 -> int32).
// ============================================================
__global__ __launch_bounds__(256) void scatter1_kernel(const int* __restrict__ ei) {
    int warp = (blockIdx.x * blockDim.x + threadIdx.x) >> 5;
    int lane = threadIdx.x & 31;
    if (warp >= EE) return;
    int src = __ldg(ei + warp);
    int dst = __ldg(ei + EE + warp);
    float4 v = reinterpret_cast<const float4*>(g_z + (size_t)src * H)[lane];
    float* ap = g_agg + (size_t)dst * H + lane * 4;
    asm volatile("red.global.add.v4.f32 [%0], {%1, %2, %3, %4};"
                 :: "l"(ap), "f"(v.x), "f"(v.y), "f"(v.z), "f"(v.w) : "memory");
}

// ============================================================
// GEMM2: g_z2[N,64] = relu(s*agg + t) @ Wg2
// Block: 64 rows x 64 cols. 256 threads; thread = 4x4 outputs.
// ============================================================
__global__ __launch_bounds__(256) void gemm2_kernel(const float* __restrict__ Wg2) {
    __shared__ float As[16][64];
    __shared__ float Bs[16][64];

    const int tid = threadIdx.x;
    const int tx = tid & 15;   // cols tx*4..+3
    const int ty = tid >> 4;   // rows ty*4..+3
    const int row0 = blockIdx.x * 64;

    float acc[4][4] = {};

    for (int kb = 0; kb < H; kb += 16) {
        // A tile with fused BN-affine + ReLU
        {
            int r  = tid >> 2;
            int kq = (tid & 3) << 2;
            int gr = row0 + r; if (gr >= NN) gr = NN - 1;
            float4 av = *reinterpret_cast<const float4*>(g_agg + (size_t)gr * H + kb + kq);
            float4 sv = *reinterpret_cast<const float4*>(g_s + kb + kq);
            float4 tv = *reinterpret_cast<const float4*>(g_t + kb + kq);
            av.x = fmaxf(av.x * sv.x + tv.x, 0.f);
            av.y = fmaxf(av.y * sv.y + tv.y, 0.f);
            av.z = fmaxf(av.z * sv.z + tv.z, 0.f);
            av.w = fmaxf(av.w * sv.w + tv.w, 0.f);
            As[kq + 0][r] = av.x; As[kq + 1][r] = av.y;
            As[kq + 2][r] = av.z; As[kq + 3][r] = av.w;
        }
        // B tile: 16 x 64 (one float4 per thread)
        {
            int k  = tid >> 4;
            int c4 = (tid & 15) << 2;
            float4 bv = *reinterpret_cast<const float4*>(Wg2 + (size_t)(kb + k) * C + c4);
            *reinterpret_cast<float4*>(&Bs[k][c4]) = bv;
        }
        __syncthreads();
        #pragma unroll
        for (int k = 0; k < 16; k++) {
            float4 a = *reinterpret_cast<const float4*>(&As[k][ty * 4]);
            float4 b = *reinterpret_cast<const float4*>(&Bs[k][tx * 4]);
            float ar[4] = {a.x, a.y, a.z, a.w};
            float br[4] = {b.x, b.y, b.z, b.w};
            #pragma unroll
            for (int i = 0; i < 4; i++)
                #pragma unroll
                for (int j = 0; j < 4; j++)
                    acc[i][j] += ar[i] * br[j];
        }
        __syncthreads();
    }

    #pragma unroll
    for (int i = 0; i < 4; i++) {
        int gr = row0 + ty * 4 + i;
        if (gr < NN) {
            float4 v = make_float4(acc[i][0], acc[i][1], acc[i][2], acc[i][3]);
            *reinterpret_cast<float4*>(g_z2 + (size_t)gr * C + tx * 4) = v;
        }
    }
}

// ============================================================
// Scatter2: out[dst] += z2[src]. 16 threads per edge (64 floats).
// ============================================================
__global__ __launch_bounds__(256) void scatter2_kernel(const int* __restrict__ ei,
                                                       float* __restrict__ out) {
    long long gid = (long long)blockIdx.x * blockDim.x + threadIdx.x;
    long long e = gid >> 4;
    int lane = (int)(gid & 15);
    if (e >= EE) return;
    int src = __ldg(ei + e);
    int dst = __ldg(ei + EE + e);
    float4 v = reinterpret_cast<const float4*>(g_z2 + (size_t)src * C)[lane];
    float* ap = out + (size_t)dst * C + lane * 4;
    asm volatile("red.global.add.v4.f32 [%0], {%1, %2, %3, %4};"
                 :: "l"(ap), "f"(v.x), "f"(v.y), "f"(v.z), "f"(v.w) : "memory");
}

// ============================================================
extern "C" void kernel_launch(void* const* d_in, const int* in_sizes, int n_in,
                              void* d_out, int out_size) {
    const float* x1    = (const float*)d_in[0];
    const float* x2    = (const float*)d_in[1];
    const int*   ei    = (const int*)d_in[2];     // int32! (jax x64 disabled)
    const float* W1    = (const float*)d_in[3];
    const float* b1    = (const float*)d_in[4];
    const float* W2    = (const float*)d_in[5];
    const float* b2    = (const float*)d_in[6];
    const float* Wg1   = (const float*)d_in[7];
    const float* bg1   = (const float*)d_in[8];
    const float* Wg2   = (const float*)d_in[9];
    const float* bg2   = (const float*)d_in[10];
    const float* gamma = (const float*)d_in[11];
    const float* beta  = (const float*)d_in[12];
    const float* rmean = (const float*)d_in[13];
    const float* rvar  = (const float*)d_in[14];
    float* out = (float*)d_out;

    prep_kernel<<<F1 + F3 + 1, H>>>(W1, b1, W2, b2, Wg1, bg1, gamma, beta, rmean, rvar);

    {
        long long tot = (long long)NN * H / 4 + (long long)NN * C / 4;
        int blocks = (int)((tot + 255) / 256);
        init_kernel<<<blocks, 256>>>(bg2, out);
    }

    gemm1_kernel<<<(NN + 63) / 64, 256>>>(x1, x2);

    {
        long long threads = (long long)EE * 32;
        scatter1_kernel<<<(int)((threads + 255) / 256), 256>>>(ei);
    }

    gemm2_kernel<<<(NN + 63) / 64, 256>>>(Wg2);

    {
        long long threads = (long long)EE * 16;
        scatter2_kernel<<<(int)((threads + 255) / 256), 256>>>(ei, out);
    }
}

// round 7
// speedup vs baseline: 1.1300x; 1.1300x over previous
#include <cuda_runtime.h>
#include <cuda_bf16.h>
#include <cstdint>

#define NN 100000
#define EE 1600000
#define F1 512
#define F3 128
#define KTOT 640
#define H  128
#define C  64
#define SW 0.2f
#define FW 0.8f
#define BN_EPS 1e-5f

// ---- scratch (device globals) ----
__device__ __nv_bfloat16 g_WhT[H * KTOT];  // [n=128][k=640]  (col-major KxN == row-major NxK)
__device__ __nv_bfloat16 g_WlT[H * KTOT];
__device__ float g_bz[H];
__device__ float g_s[H];
__device__ float g_t[H];
__device__ float g_z[(size_t)NN * H];
__device__ float g_agg[(size_t)NN * H];
__device__ float g_z2[(size_t)NN * C];

// ============================================================
// Prolog: combined weights -> bf16 hi/lo (transposed) + BN affine.
// ============================================================
__global__ void prep_kernel(const float* __restrict__ W1, const float* __restrict__ b1,
                            const float* __restrict__ W2, const float* __restrict__ b2,
                            const float* __restrict__ Wg1, const float* __restrict__ bg1,
                            const float* __restrict__ gamma, const float* __restrict__ beta,
                            const float* __restrict__ rmean, const float* __restrict__ rvar) {
    int j = threadIdx.x;   // output column 0..127
    int b = blockIdx.x;    // k row
    __shared__ float a[H];
    if (b < KTOT) {
        float scale = (b < F1) ? FW : SW;
        a[j] = (b < F1) ? W1[b * H + j] : W2[(b - F1) * H + j];
        __syncthreads();
        float acc = 0.f;
        #pragma unroll 8
        for (int k = 0; k < H; k++) acc += a[k] * Wg1[k * H + j];
        acc *= scale;
        __nv_bfloat16 hi = __float2bfloat16(acc);
        __nv_bfloat16 lo = __float2bfloat16(acc - __bfloat162float(hi));
        g_WhT[j * KTOT + b] = hi;
        g_WlT[j * KTOT + b] = lo;
    } else {
        a[j] = FW * b1[j] + SW * b2[j];
        __syncthreads();
        float acc = 0.f;
        #pragma unroll 8
        for (int k = 0; k < H; k++) acc += a[k] * Wg1[k * H + j];
        g_bz[j] = acc;
        float sc = gamma[j] * rsqrtf(rvar[j] + BN_EPS);
        g_s[j] = sc;
        g_t[j] = (bg1[j] - rmean[j]) * sc + beta[j];
    }
}

// ============================================================
// Init: zero g_agg, out = bg2.
// ============================================================
__global__ void init_kernel(const float* __restrict__ bg2, float* __restrict__ out) {
    const long long AGG4 = (long long)NN * H / 4;
    const long long OUT4 = (long long)NN * C / 4;
    long long i = (long long)blockIdx.x * blockDim.x + threadIdx.x;
    if (i < AGG4) {
        reinterpret_cast<float4*>(g_agg)[i] = make_float4(0.f, 0.f, 0.f, 0.f);
    } else {
        long long o = i - AGG4;
        if (o < OUT4) {
            float4 v = reinterpret_cast<const float4*>(bg2)[o & (C / 4 - 1)];
            reinterpret_cast<float4*>(out)[o] = v;
        }
    }
}

// ============================================================
// GEMM1 (HMMA): z[128 x 128] tiles = x @ Wh + x_hi @ Wl + bz
// mma.sync m16n8k16 bf16, 3-pass hi/lo split, K chunks of 32.
// APAD = 40 elements (80 B row stride): 16B-aligned uint4 stores,
// conflict-free fragment loads (20 words * gq spans all banks).
// ============================================================
#define KC    32          // k per chunk
#define APAD  40          // padded k stride (bf16) for A/B smem
#define NCH   (KTOT / KC) // 20 chunks

__device__ __forceinline__ void hmma(float* d, const uint32_t* a, const uint32_t* b) {
    asm volatile(
        "mma.sync.aligned.m16n8k16.row.col.f32.bf16.bf16.f32 "
        "{%0,%1,%2,%3}, {%4,%5,%6,%7}, {%8,%9}, {%0,%1,%2,%3};"
        : "+f"(d[0]), "+f"(d[1]), "+f"(d[2]), "+f"(d[3])
        : "r"(a[0]), "r"(a[1]), "r"(a[2]), "r"(a[3]), "r"(b[0]), "r"(b[1]));
}

__global__ __launch_bounds__(256) void gemm1_mma(const float* __restrict__ x1,
                                                 const float* __restrict__ x2) {
    __shared__ __nv_bfloat16 sA[2][128][APAD];  // [hi/lo][m][k]
    __shared__ __nv_bfloat16 sB[2][128][APAD];  // [hi/lo][n][k]

    const int tid  = threadIdx.x;
    const int wid  = tid >> 5;
    const int lane = tid & 31;
    const int wm   = (wid & 3) * 32;   // warp m base (4 warps down)
    const int wn   = (wid >> 2) * 64;  // warp n base (2 warps across)
    const int row0 = blockIdx.x * 128;

    const int gq = lane >> 2;          // fragment group row (0..7)
    const int qq = (lane & 3) * 2;     // fragment k/col pair base

    float acc[2][8][4];
    #pragma unroll
    for (int i = 0; i < 2; i++)
        #pragma unroll
        for (int j = 0; j < 8; j++)
            #pragma unroll
            for (int q = 0; q < 4; q++) acc[i][j][q] = 0.f;

    // per-thread staging roles
    const int ar  = tid >> 1;                 // A row / B n-row (0..127)
    const int ah  = (tid & 1) * 16;           // k half offset (16 elements)
    const int gr  = min(row0 + ar, NN - 1);

    for (int ch = 0; ch < NCH; ch++) {
        const int k0 = ch * KC;
        // ---- stage A: 16 fp32 -> bf16 hi/lo ----
        {
            const float* xr = (k0 < F1) ? (x1 + (size_t)gr * F1 + k0 + ah)
                                        : (x2 + (size_t)gr * F3 + (k0 - F1) + ah);
            #pragma unroll
            for (int v = 0; v < 4; v++) {
                float4 f = *reinterpret_cast<const float4*>(xr + v * 4);
                __nv_bfloat16 h0 = __float2bfloat16(f.x), h1 = __float2bfloat16(f.y);
                __nv_bfloat16 h2 = __float2bfloat16(f.z), h3 = __float2bfloat16(f.w);
                sA[0][ar][ah + v * 4 + 0] = h0;
                sA[0][ar][ah + v * 4 + 1] = h1;
                sA[0][ar][ah + v * 4 + 2] = h2;
                sA[0][ar][ah + v * 4 + 3] = h3;
                sA[1][ar][ah + v * 4 + 0] = __float2bfloat16(f.x - __bfloat162float(h0));
                sA[1][ar][ah + v * 4 + 1] = __float2bfloat16(f.y - __bfloat162float(h1));
                sA[1][ar][ah + v * 4 + 2] = __float2bfloat16(f.z - __bfloat162float(h2));
                sA[1][ar][ah + v * 4 + 3] = __float2bfloat16(f.w - __bfloat162float(h3));
            }
        }
        // ---- stage B: 16 bf16 hi + 16 lo (16B-aligned with APAD=40) ----
        {
            const uint4* bh = reinterpret_cast<const uint4*>(g_WhT + (size_t)ar * KTOT + k0 + ah);
            const uint4* bl = reinterpret_cast<const uint4*>(g_WlT + (size_t)ar * KTOT + k0 + ah);
            uint4 h0 = bh[0], h1 = bh[1], l0 = bl[0], l1 = bl[1];
            *reinterpret_cast<uint4*>(&sB[0][ar][ah])     = h0;
            *reinterpret_cast<uint4*>(&sB[0][ar][ah + 8]) = h1;
            *reinterpret_cast<uint4*>(&sB[1][ar][ah])     = l0;
            *reinterpret_cast<uint4*>(&sB[1][ar][ah + 8]) = l1;
        }
        __syncthreads();

        // ---- compute: 3 passes x 2 k-steps x (2m x 8n) mma ----
        #pragma unroll
        for (int pass = 0; pass < 3; pass++) {
            const int ab = (pass == 1) ? 1 : 0;   // A buffer (hi,lo,hi)
            const int bb = (pass == 2) ? 1 : 0;   // B buffer (hi,hi,lo)
            #pragma unroll
            for (int ks = 0; ks < 2; ks++) {
                const int kk = ks * 16;
                uint32_t afr[2][4];
                #pragma unroll
                for (int mt = 0; mt < 2; mt++) {
                    const int mr = wm + mt * 16 + gq;
                    afr[mt][0] = *reinterpret_cast<const uint32_t*>(&sA[ab][mr    ][kk + qq]);
                    afr[mt][1] = *reinterpret_cast<const uint32_t*>(&sA[ab][mr + 8][kk + qq]);
                    afr[mt][2] = *reinterpret_cast<const uint32_t*>(&sA[ab][mr    ][kk + qq + 8]);
                    afr[mt][3] = *reinterpret_cast<const uint32_t*>(&sA[ab][mr + 8][kk + qq + 8]);
                }
                #pragma unroll
                for (int nt = 0; nt < 8; nt++) {
                    const int nr = wn + nt * 8 + gq;
                    uint32_t bfr[2];
                    bfr[0] = *reinterpret_cast<const uint32_t*>(&sB[bb][nr][kk + qq]);
                    bfr[1] = *reinterpret_cast<const uint32_t*>(&sB[bb][nr][kk + qq + 8]);
                    hmma(acc[0][nt], afr[0], bfr);
                    hmma(acc[1][nt], afr[1], bfr);
                }
            }
        }
        __syncthreads();
    }

    // ---- epilogue: + bz -> g_z ----
    #pragma unroll
    for (int mt = 0; mt < 2; mt++) {
        const int r0 = row0 + wm + mt * 16 + gq;
        const int r1 = r0 + 8;
        #pragma unroll
        for (int nt = 0; nt < 8; nt++) {
            const int cc = wn + nt * 8 + qq;
            float2 bz = *reinterpret_cast<const float2*>(g_bz + cc);
            if (r0 < NN) {
                float2 v = make_float2(acc[mt][nt][0] + bz.x, acc[mt][nt][1] + bz.y);
                *reinterpret_cast<float2*>(g_z + (size_t)r0 * H + cc) = v;
            }
            if (r1 < NN) {
                float2 v = make_float2(acc[mt][nt][2] + bz.x, acc[mt][nt][3] + bz.y);
                *reinterpret_cast<float2*>(g_z + (size_t)r1 * H + cc) = v;
            }
        }
    }
}

// ============================================================
// Scatter1: agg[dst] += z[src].  Warp per edge, RED.128.
// ============================================================
__global__ __launch_bounds__(256) void scatter1_kernel(const int* __restrict__ ei) {
    int warp = (blockIdx.x * blockDim.x + threadIdx.x) >> 5;
    int lane = threadIdx.x & 31;
    if (warp >= EE) return;
    int src = __ldg(ei + warp);
    int dst = __ldg(ei + EE + warp);
    float4 v = reinterpret_cast<const float4*>(g_z + (size_t)src * H)[lane];
    float* ap = g_agg + (size_t)dst * H + lane * 4;
    asm volatile("red.global.add.v4.f32 [%0], {%1, %2, %3, %4};"
                 :: "l"(ap), "f"(v.x), "f"(v.y), "f"(v.z), "f"(v.w) : "memory");
}

// ============================================================
// GEMM2: g_z2[N,64] = relu(s*agg + t) @ Wg2   (SIMT)
// ============================================================
__global__ __launch_bounds__(256) void gemm2_kernel(const float* __restrict__ Wg2) {
    __shared__ float As[16][64];
    __shared__ float Bs[16][64];
    const int tid = threadIdx.x;
    const int tx = tid & 15;
    const int ty = tid >> 4;
    const int row0 = blockIdx.x * 64;
    float acc[4][4] = {};

    for (int kb = 0; kb < H; kb += 16) {
        {
            int r  = tid >> 2;
            int kq = (tid & 3) << 2;
            int gr = row0 + r; if (gr >= NN) gr = NN - 1;
            float4 av = *reinterpret_cast<const float4*>(g_agg + (size_t)gr * H + kb + kq);
            float4 sv = *reinterpret_cast<const float4*>(g_s + kb + kq);
            float4 tv = *reinterpret_cast<const float4*>(g_t + kb + kq);
            av.x = fmaxf(av.x * sv.x + tv.x, 0.f);
            av.y = fmaxf(av.y * sv.y + tv.y, 0.f);
            av.z = fmaxf(av.z * sv.z + tv.z, 0.f);
            av.w = fmaxf(av.w * sv.w + tv.w, 0.f);
            As[kq + 0][r] = av.x; As[kq + 1][r] = av.y;
            As[kq + 2][r] = av.z; As[kq + 3][r] = av.w;
        }
        {
            int k  = tid >> 4;
            int c4 = (tid & 15) << 2;
            float4 bv = *reinterpret_cast<const float4*>(Wg2 + (size_t)(kb + k) * C + c4);
            *reinterpret_cast<float4*>(&Bs[k][c4]) = bv;
        }
        __syncthreads();
        #pragma unroll
        for (int k = 0; k < 16; k++) {
            float4 a = *reinterpret_cast<const float4*>(&As[k][ty * 4]);
            float4 b = *reinterpret_cast<const float4*>(&Bs[k][tx * 4]);
            float ar[4] = {a.x, a.y, a.z, a.w};
            float br[4] = {b.x, b.y, b.z, b.w};
            #pragma unroll
            for (int i = 0; i < 4; i++)
                #pragma unroll
                for (int j = 0; j < 4; j++)
                    acc[i][j] += ar[i] * br[j];
        }
        __syncthreads();
    }
    #pragma unroll
    for (int i = 0; i < 4; i++) {
        int gr = row0 + ty * 4 + i;
        if (gr < NN) {
            float4 v = make_float4(acc[i][0], acc[i][1], acc[i][2], acc[i][3]);
            *reinterpret_cast<float4*>(g_z2 + (size_t)gr * C + tx * 4) = v;
        }
    }
}

// ============================================================
// Scatter2: out[dst] += z2[src]. 16 threads/edge, RED.128.
// ============================================================
__global__ __launch_bounds__(256) void scatter2_kernel(const int* __restrict__ ei,
                                                       float* __restrict__ out) {
    long long gid = (long long)blockIdx.x * blockDim.x + threadIdx.x;
    long long e = gid >> 4;
    int lane = (int)(gid & 15);
    if (e >= EE) return;
    int src = __ldg(ei + e);
    int dst = __ldg(ei + EE + e);
    float4 v = reinterpret_cast<const float4*>(g_z2 + (size_t)src * C)[lane];
    float* ap = out + (size_t)dst * C + lane * 4;
    asm volatile("red.global.add.v4.f32 [%0], {%1, %2, %3, %4};"
                 :: "l"(ap), "f"(v.x), "f"(v.y), "f"(v.z), "f"(v.w) : "memory");
}

// ============================================================
extern "C" void kernel_launch(void* const* d_in, const int* in_sizes, int n_in,
                              void* d_out, int out_size) {
    const float* x1    = (const float*)d_in[0];
    const float* x2    = (const float*)d_in[1];
    const int*   ei    = (const int*)d_in[2];
    const float* W1    = (const float*)d_in[3];
    const float* b1    = (const float*)d_in[4];
    const float* W2    = (const float*)d_in[5];
    const float* b2    = (const float*)d_in[6];
    const float* Wg1   = (const float*)d_in[7];
    const float* bg1   = (const float*)d_in[8];
    const float* Wg2   = (const float*)d_in[9];
    const float* bg2   = (const float*)d_in[10];
    const float* gamma = (const float*)d_in[11];
    const float* beta  = (const float*)d_in[12];
    const float* rmean = (const float*)d_in[13];
    const float* rvar  = (const float*)d_in[14];
    float* out = (float*)d_out;

    prep_kernel<<<KTOT + 1, H>>>(W1, b1, W2, b2, Wg1, bg1, gamma, beta, rmean, rvar);

    {
        long long tot = (long long)NN * H / 4 + (long long)NN * C / 4;
        init_kernel<<<(int)((tot + 255) / 256), 256>>>(bg2, out);
    }

    gemm1_mma<<<(NN + 127) / 128, 256>>>(x1, x2);

    {
        long long threads = (long long)EE * 32;
        scatter1_kernel<<<(int)((threads + 255) / 256), 256>>>(ei);
    }

    gemm2_kernel<<<(NN + 63) / 64, 256>>>(Wg2);

    {
        long long threads = (long long)EE * 16;
        scatter2_kernel<<<(int)((threads + 255) / 256), 256>>>(ei, out);
    }
}

// round 8
// speedup vs baseline: 1.2628x; 1.1175x over previous
#include <cuda_runtime.h>
#include <cuda_bf16.h>
#include <cstdint>

#define NN 100000
#define EE 1600000
#define F1 512
#define F3 128
#define KTOT 640
#define H  128
#define C  64
#define SW 0.2f
#define FW 0.8f
#define BN_EPS 1e-5f

// ---- scratch (device globals) ----
__device__ __nv_bfloat16 g_WhT[H * KTOT];  // [n=128][k=640]
__device__ __nv_bfloat16 g_WlT[H * KTOT];
__device__ float g_bz[H];
__device__ float g_s[H];
__device__ float g_t[H];
__device__ float g_z[(size_t)NN * H];
__device__ float g_agg[(size_t)NN * H];
__device__ float g_z2[(size_t)NN * C];

// ============================================================
// Prolog: combined weights -> bf16 hi/lo (transposed) + BN affine.
// ============================================================
__global__ void prep_kernel(const float* __restrict__ W1, const float* __restrict__ b1,
                            const float* __restrict__ W2, const float* __restrict__ b2,
                            const float* __restrict__ Wg1, const float* __restrict__ bg1,
                            const float* __restrict__ gamma, const float* __restrict__ beta,
                            const float* __restrict__ rmean, const float* __restrict__ rvar) {
    int j = threadIdx.x;
    int b = blockIdx.x;
    __shared__ float a[H];
    if (b < KTOT) {
        float scale = (b < F1) ? FW : SW;
        a[j] = (b < F1) ? W1[b * H + j] : W2[(b - F1) * H + j];
        __syncthreads();
        float acc = 0.f;
        #pragma unroll 8
        for (int k = 0; k < H; k++) acc += a[k] * Wg1[k * H + j];
        acc *= scale;
        __nv_bfloat16 hi = __float2bfloat16(acc);
        __nv_bfloat16 lo = __float2bfloat16(acc - __bfloat162float(hi));
        g_WhT[j * KTOT + b] = hi;
        g_WlT[j * KTOT + b] = lo;
    } else {
        a[j] = FW * b1[j] + SW * b2[j];
        __syncthreads();
        float acc = 0.f;
        #pragma unroll 8
        for (int k = 0; k < H; k++) acc += a[k] * Wg1[k * H + j];
        g_bz[j] = acc;
        float sc = gamma[j] * rsqrtf(rvar[j] + BN_EPS);
        g_s[j] = sc;
        g_t[j] = (bg1[j] - rmean[j]) * sc + beta[j];
    }
}

// ============================================================
// Init: zero g_agg, out = bg2.
// ============================================================
__global__ void init_kernel(const float* __restrict__ bg2, float* __restrict__ out) {
    const long long AGG4 = (long long)NN * H / 4;
    const long long OUT4 = (long long)NN * C / 4;
    long long i = (long long)blockIdx.x * blockDim.x + threadIdx.x;
    if (i < AGG4) {
        reinterpret_cast<float4*>(g_agg)[i] = make_float4(0.f, 0.f, 0.f, 0.f);
    } else {
        long long o = i - AGG4;
        if (o < OUT4) {
            float4 v = reinterpret_cast<const float4*>(bg2)[o & (C / 4 - 1)];
            reinterpret_cast<float4*>(out)[o] = v;
        }
    }
}

// ============================================================
// GEMM1 (HMMA): z[128 x 128] tiles = x @ Wh + x_hi @ Wl + bz
// mma.sync m16n8k16 bf16, 3-pass hi/lo split, K chunks of 32.
// Packed STS.128 staging + register prefetch pipeline.
// ============================================================
#define KC    32
#define APAD  40          // 80B row stride: STS.128-aligned, conflict-free frags
#define NCH   (KTOT / KC)

__device__ __forceinline__ void hmma(float* d, const uint32_t* a, const uint32_t* b) {
    asm volatile(
        "mma.sync.aligned.m16n8k16.row.col.f32.bf16.bf16.f32 "
        "{%0,%1,%2,%3}, {%4,%5,%6,%7}, {%8,%9}, {%0,%1,%2,%3};"
        : "+f"(d[0]), "+f"(d[1]), "+f"(d[2]), "+f"(d[3])
        : "r"(a[0]), "r"(a[1]), "r"(a[2]), "r"(a[3]), "r"(b[0]), "r"(b[1]));
}

__global__ __launch_bounds__(256) void gemm1_mma(const float* __restrict__ x1,
                                                 const float* __restrict__ x2) {
    __shared__ __nv_bfloat16 sA[2][128][APAD];  // [hi/lo][m][k]
    __shared__ __nv_bfloat16 sB[2][128][APAD];  // [hi/lo][n][k]

    const int tid  = threadIdx.x;
    const int wid  = tid >> 5;
    const int lane = tid & 31;
    const int wm   = (wid & 3) * 32;
    const int wn   = (wid >> 2) * 64;
    const int row0 = blockIdx.x * 128;

    const int gq = lane >> 2;
    const int qq = (lane & 3) * 2;

    float acc[2][8][4];
    #pragma unroll
    for (int i = 0; i < 2; i++)
        #pragma unroll
        for (int j = 0; j < 8; j++)
            #pragma unroll
            for (int q = 0; q < 4; q++) acc[i][j][q] = 0.f;

    // staging roles: thread -> (row, k-half)
    const int ar = tid >> 1;
    const int ah = (tid & 1) * 16;
    const int gr = min(row0 + ar, NN - 1);

    // ---- prefetch registers ----
    float4 fa[4];
    uint4  fbh[2], fbl[2];

    auto load_chunk = [&](int ch) {
        const int k0 = ch * KC;
        const float* xr = (k0 < F1) ? (x1 + (size_t)gr * F1 + k0 + ah)
                                    : (x2 + (size_t)gr * F3 + (k0 - F1) + ah);
        #pragma unroll
        for (int v = 0; v < 4; v++)
            fa[v] = __ldg(reinterpret_cast<const float4*>(xr) + v);
        const uint4* bh = reinterpret_cast<const uint4*>(g_WhT + (size_t)ar * KTOT + k0 + ah);
        const uint4* bl = reinterpret_cast<const uint4*>(g_WlT + (size_t)ar * KTOT + k0 + ah);
        fbh[0] = bh[0]; fbh[1] = bh[1];
        fbl[0] = bl[0]; fbl[1] = bl[1];
    };

    load_chunk(0);

    for (int ch = 0; ch < NCH; ch++) {
        // ---- stage from registers: pack bf16x2, STS.128 ----
        {
            uint32_t hw[8], lw[8];
            #pragma unroll
            for (int v = 0; v < 4; v++) {
                float4 f = fa[v];
                __nv_bfloat162 h01 = __floats2bfloat162_rn(f.x, f.y);
                __nv_bfloat162 h23 = __floats2bfloat162_rn(f.z, f.w);
                hw[v * 2 + 0] = *reinterpret_cast<uint32_t*>(&h01);
                hw[v * 2 + 1] = *reinterpret_cast<uint32_t*>(&h23);
                __nv_bfloat162 l01 = __floats2bfloat162_rn(f.x - __bfloat162float(h01.x),
                                                           f.y - __bfloat162float(h01.y));
                __nv_bfloat162 l23 = __floats2bfloat162_rn(f.z - __bfloat162float(h23.x),
                                                           f.w - __bfloat162float(h23.y));
                lw[v * 2 + 0] = *reinterpret_cast<uint32_t*>(&l01);
                lw[v * 2 + 1] = *reinterpret_cast<uint32_t*>(&l23);
            }
            *reinterpret_cast<uint4*>(&sA[0][ar][ah])     = make_uint4(hw[0], hw[1], hw[2], hw[3]);
            *reinterpret_cast<uint4*>(&sA[0][ar][ah + 8]) = make_uint4(hw[4], hw[5], hw[6], hw[7]);
            *reinterpret_cast<uint4*>(&sA[1][ar][ah])     = make_uint4(lw[0], lw[1], lw[2], lw[3]);
            *reinterpret_cast<uint4*>(&sA[1][ar][ah + 8]) = make_uint4(lw[4], lw[5], lw[6], lw[7]);
            *reinterpret_cast<uint4*>(&sB[0][ar][ah])     = fbh[0];
            *reinterpret_cast<uint4*>(&sB[0][ar][ah + 8]) = fbh[1];
            *reinterpret_cast<uint4*>(&sB[1][ar][ah])     = fbl[0];
            *reinterpret_cast<uint4*>(&sB[1][ar][ah + 8]) = fbl[1];
        }
        __syncthreads();

        // ---- prefetch next chunk (overlaps with compute below) ----
        if (ch + 1 < NCH) load_chunk(ch + 1);

        // ---- compute: 3 passes x 2 k-steps x (2m x 8n) mma ----
        #pragma unroll
        for (int pass = 0; pass < 3; pass++) {
            const int ab = (pass == 1) ? 1 : 0;
            const int bb = (pass == 2) ? 1 : 0;
            #pragma unroll
            for (int ks = 0; ks < 2; ks++) {
                const int kk = ks * 16;
                uint32_t afr[2][4];
                #pragma unroll
                for (int mt = 0; mt < 2; mt++) {
                    const int mr = wm + mt * 16 + gq;
                    afr[mt][0] = *reinterpret_cast<const uint32_t*>(&sA[ab][mr    ][kk + qq]);
                    afr[mt][1] = *reinterpret_cast<const uint32_t*>(&sA[ab][mr + 8][kk + qq]);
                    afr[mt][2] = *reinterpret_cast<const uint32_t*>(&sA[ab][mr    ][kk + qq + 8]);
                    afr[mt][3] = *reinterpret_cast<const uint32_t*>(&sA[ab][mr + 8][kk + qq + 8]);
                }
                #pragma unroll
                for (int nt = 0; nt < 8; nt++) {
                    const int nr = wn + nt * 8 + gq;
                    uint32_t bfr[2];
                    bfr[0] = *reinterpret_cast<const uint32_t*>(&sB[bb][nr][kk + qq]);
                    bfr[1] = *reinterpret_cast<const uint32_t*>(&sB[bb][nr][kk + qq + 8]);
                    hmma(acc[0][nt], afr[0], bfr);
                    hmma(acc[1][nt], afr[1], bfr);
                }
            }
        }
        __syncthreads();
    }

    // ---- epilogue: + bz -> g_z ----
    #pragma unroll
    for (int mt = 0; mt < 2; mt++) {
        const int r0 = row0 + wm + mt * 16 + gq;
        const int r1 = r0 + 8;
        #pragma unroll
        for (int nt = 0; nt < 8; nt++) {
            const int cc = wn + nt * 8 + qq;
            float2 bz = *reinterpret_cast<const float2*>(g_bz + cc);
            if (r0 < NN) {
                float2 v = make_float2(acc[mt][nt][0] + bz.x, acc[mt][nt][1] + bz.y);
                *reinterpret_cast<float2*>(g_z + (size_t)r0 * H + cc) = v;
            }
            if (r1 < NN) {
                float2 v = make_float2(acc[mt][nt][2] + bz.x, acc[mt][nt][3] + bz.y);
                *reinterpret_cast<float2*>(g_z + (size_t)r1 * H + cc) = v;
            }
        }
    }
}

// ============================================================
// Scatter1: agg[dst] += z[src].  Warp per edge, RED.128.
// ============================================================
__global__ __launch_bounds__(256) void scatter1_kernel(const int* __restrict__ ei) {
    int warp = (blockIdx.x * blockDim.x + threadIdx.x) >> 5;
    int lane = threadIdx.x & 31;
    if (warp >= EE) return;
    int src = __ldg(ei + warp);
    int dst = __ldg(ei + EE + warp);
    float4 v = reinterpret_cast<const float4*>(g_z + (size_t)src * H)[lane];
    float* ap = g_agg + (size_t)dst * H + lane * 4;
    asm volatile("red.global.add.v4.f32 [%0], {%1, %2, %3, %4};"
                 :: "l"(ap), "f"(v.x), "f"(v.y), "f"(v.z), "f"(v.w) : "memory");
}

// ============================================================
// GEMM2: g_z2[N,64] = relu(s*agg + t) @ Wg2   (SIMT)
// ============================================================
__global__ __launch_bounds__(256) void gemm2_kernel(const float* __restrict__ Wg2) {
    __shared__ float As[16][64];
    __shared__ float Bs[16][64];
    const int tid = threadIdx.x;
    const int tx = tid & 15;
    const int ty = tid >> 4;
    const int row0 = blockIdx.x * 64;
    float acc[4][4] = {};

    for (int kb = 0; kb < H; kb += 16) {
        {
            int r  = tid >> 2;
            int kq = (tid & 3) << 2;
            int gr = row0 + r; if (gr >= NN) gr = NN - 1;
            float4 av = *reinterpret_cast<const float4*>(g_agg + (size_t)gr * H + kb + kq);
            float4 sv = *reinterpret_cast<const float4*>(g_s + kb + kq);
            float4 tv = *reinterpret_cast<const float4*>(g_t + kb + kq);
            av.x = fmaxf(av.x * sv.x + tv.x, 0.f);
            av.y = fmaxf(av.y * sv.y + tv.y, 0.f);
            av.z = fmaxf(av.z * sv.z + tv.z, 0.f);
            av.w = fmaxf(av.w * sv.w + tv.w, 0.f);
            As[kq + 0][r] = av.x; As[kq + 1][r] = av.y;
            As[kq + 2][r] = av.z; As[kq + 3][r] = av.w;
        }
        {
            int k  = tid >> 4;
            int c4 = (tid & 15) << 2;
            float4 bv = *reinterpret_cast<const float4*>(Wg2 + (size_t)(kb + k) * C + c4);
            *reinterpret_cast<float4*>(&Bs[k][c4]) = bv;
        }
        __syncthreads();
        #pragma unroll
        for (int k = 0; k < 16; k++) {
            float4 a = *reinterpret_cast<const float4*>(&As[k][ty * 4]);
            float4 b = *reinterpret_cast<const float4*>(&Bs[k][tx * 4]);
            float ar[4] = {a.x, a.y, a.z, a.w};
            float br[4] = {b.x, b.y, b.z, b.w};
            #pragma unroll
            for (int i = 0; i < 4; i++)
                #pragma unroll
                for (int j = 0; j < 4; j++)
                    acc[i][j] += ar[i] * br[j];
        }
        __syncthreads();
    }
    #pragma unroll
    for (int i = 0; i < 4; i++) {
        int gr = row0 + ty * 4 + i;
        if (gr < NN) {
            float4 v = make_float4(acc[i][0], acc[i][1], acc[i][2], acc[i][3]);
            *reinterpret_cast<float4*>(g_z2 + (size_t)gr * C + tx * 4) = v;
        }
    }
}

// ============================================================
// Scatter2: out[dst] += z2[src]. 16 threads/edge, RED.128.
// ============================================================
__global__ __launch_bounds__(256) void scatter2_kernel(const int* __restrict__ ei,
                                                       float* __restrict__ out) {
    long long gid = (long long)blockIdx.x * blockDim.x + threadIdx.x;
    long long e = gid >> 4;
    int lane = (int)(gid & 15);
    if (e >= EE) return;
    int src = __ldg(ei + e);
    int dst = __ldg(ei + EE + e);
    float4 v = reinterpret_cast<const float4*>(g_z2 + (size_t)src * C)[lane];
    float* ap = out + (size_t)dst * C + lane * 4;
    asm volatile("red.global.add.v4.f32 [%0], {%1, %2, %3, %4};"
                 :: "l"(ap), "f"(v.x), "f"(v.y), "f"(v.z), "f"(v.w) : "memory");
}

// ============================================================
extern "C" void kernel_launch(void* const* d_in, const int* in_sizes, int n_in,
                              void* d_out, int out_size) {
    const float* x1    = (const float*)d_in[0];
    const float* x2    = (const float*)d_in[1];
    const int*   ei    = (const int*)d_in[2];
    const float* W1    = (const float*)d_in[3];
    const float* b1    = (const float*)d_in[4];
    const float* W2    = (const float*)d_in[5];
    const float* b2    = (const float*)d_in[6];
    const float* Wg1   = (const float*)d_in[7];
    const float* bg1   = (const float*)d_in[8];
    const float* Wg2   = (const float*)d_in[9];
    const float* bg2   = (const float*)d_in[10];
    const float* gamma = (const float*)d_in[11];
    const float* beta  = (const float*)d_in[12];
    const float* rmean = (const float*)d_in[13];
    const float* rvar  = (const float*)d_in[14];
    float* out = (float*)d_out;

    prep_kernel<<<KTOT + 1, H>>>(W1, b1, W2, b2, Wg1, bg1, gamma, beta, rmean, rvar);

    {
        long long tot = (long long)NN * H / 4 + (long long)NN * C / 4;
        init_kernel<<<(int)((tot + 255) / 256), 256>>>(bg2, out);
    }

    gemm1_mma<<<(NN + 127) / 128, 256>>>(x1, x2);

    {
        long long threads = (long long)EE * 32;
        scatter1_kernel<<<(int)((threads + 255) / 256), 256>>>(ei);
    }

    gemm2_kernel<<<(NN + 63) / 64, 256>>>(Wg2);

    {
        long long threads = (long long)EE * 16;
        scatter2_kernel<<<(int)((threads + 255) / 256), 256>>>(ei, out);
    }
}

// round 11
// speedup vs baseline: 1.8057x; 1.4300x over previous
#include <cuda_runtime.h>
#include <cuda_bf16.h>
#include <cstdint>

#define NN 100000
#define EE 1600000
#define F1 512
#define F3 128
#define KTOT 640
#define H  128
#define C  64
#define SW 0.2f
#define FW 0.8f
#define BN_EPS 1e-5f

#define SCAN_B 512
#define NB1 ((NN + SCAN_B - 1) / SCAN_B)   // 196

// ---- scratch (device globals) ----
__device__ __nv_bfloat16 g_WhT[H * KTOT];
__device__ __nv_bfloat16 g_WlT[H * KTOT];
__device__ float g_bz[H];
__device__ float g_s[H];
__device__ float g_t[H];
__device__ float g_z[(size_t)NN * H];
__device__ float g_agg[(size_t)NN * H];   // post-BN+ReLU activations
__device__ float g_z2[(size_t)NN * C];
__device__ int   g_cnt[NN];               // histogram -> cursor
__device__ int   g_off[NN + 1];           // exclusive prefix (CSR offsets)
__device__ int   g_eid[EE];               // src ids bucketed by dst
__device__ int   g_bsum[NB1];

// ============================================================
// Prolog: combined weights -> bf16 hi/lo (transposed) + BN affine.
// ============================================================
__global__ void prep_kernel(const float* __restrict__ W1, const float* __restrict__ b1,
                            const float* __restrict__ W2, const float* __restrict__ b2,
                            const float* __restrict__ Wg1, const float* __restrict__ bg1,
                            const float* __restrict__ gamma, const float* __restrict__ beta,
                            const float* __restrict__ rmean, const float* __restrict__ rvar) {
    int j = threadIdx.x;
    int b = blockIdx.x;
    __shared__ float a[H];
    if (b < KTOT) {
        float scale = (b < F1) ? FW : SW;
        a[j] = (b < F1) ? W1[b * H + j] : W2[(b - F1) * H + j];
        __syncthreads();
        float acc = 0.f;
        #pragma unroll 8
        for (int k = 0; k < H; k++) acc += a[k] * Wg1[k * H + j];
        acc *= scale;
        __nv_bfloat16 hi = __float2bfloat16(acc);
        __nv_bfloat16 lo = __float2bfloat16(acc - __bfloat162float(hi));
        g_WhT[j * KTOT + b] = hi;
        g_WlT[j * KTOT + b] = lo;
    } else {
        a[j] = FW * b1[j] + SW * b2[j];
        __syncthreads();
        float acc = 0.f;
        #pragma unroll 8
        for (int k = 0; k < H; k++) acc += a[k] * Wg1[k * H + j];
        g_bz[j] = acc;
        float sc = gamma[j] * rsqrtf(rvar[j] + BN_EPS);
        g_s[j] = sc;
        g_t[j] = (bg1[j] - rmean[j]) * sc + beta[j];
    }
}

// ============================================================
// Counting sort of edges by dst.
// ============================================================
__global__ void zero_cnt_kernel() {
    int i = blockIdx.x * blockDim.x + threadIdx.x;
    if (i < NN) g_cnt[i] = 0;
}

__global__ void hist_kernel(const int* __restrict__ ei) {
    int e = blockIdx.x * blockDim.x + threadIdx.x;
    if (e >= EE) return;
    atomicAdd(&g_cnt[__ldg(ei + EE + e)], 1);
}

__global__ __launch_bounds__(SCAN_B) void scan1_kernel() {
    __shared__ int s[SCAN_B];
    int tid = threadIdx.x;
    int i = blockIdx.x * SCAN_B + tid;
    int v = (i < NN) ? g_cnt[i] : 0;
    s[tid] = v;
    __syncthreads();
    #pragma unroll
    for (int d = 1; d < SCAN_B; d <<= 1) {
        int t = (tid >= d) ? s[tid - d] : 0;
        __syncthreads();
        s[tid] += t;
        __syncthreads();
    }
    if (i < NN) g_off[i] = s[tid] - v;     // exclusive
    if (tid == SCAN_B - 1) g_bsum[blockIdx.x] = s[tid];
}

__global__ __launch_bounds__(256) void scan2_kernel() {
    __shared__ int s[256];
    int tid = threadIdx.x;
    int v = (tid < NB1) ? g_bsum[tid] : 0;
    s[tid] = v;
    __syncthreads();
    #pragma unroll
    for (int d = 1; d < 256; d <<= 1) {
        int t = (tid >= d) ? s[tid - d] : 0;
        __syncthreads();
        s[tid] += t;
        __syncthreads();
    }
    if (tid < NB1) g_bsum[tid] = s[tid] - v;  // exclusive
}

__global__ __launch_bounds__(SCAN_B) void scan3_kernel() {
    int i = blockIdx.x * SCAN_B + threadIdx.x;
    if (i < NN) {
        int o = g_off[i] + g_bsum[blockIdx.x];
        g_off[i] = o;
        g_cnt[i] = o;                      // cursor for fill
    }
    if (i == 0) g_off[NN] = EE;
}

__global__ void fill_kernel(const int* __restrict__ ei) {
    int e = blockIdx.x * blockDim.x + threadIdx.x;
    if (e >= EE) return;
    int src = __ldg(ei + e);
    int dst = __ldg(ei + EE + e);
    int pos = atomicAdd(&g_cnt[dst], 1);
    g_eid[pos] = src;
}

// ============================================================
// GEMM1 (HMMA): z = x @ Wh + x_hi @ Wl + bz   (unchanged from R7)
// ============================================================
#define KC    32
#define APAD  40
#define NCH   (KTOT / KC)

__device__ __forceinline__ void hmma(float* d, const uint32_t* a, const uint32_t* b) {
    asm volatile(
        "mma.sync.aligned.m16n8k16.row.col.f32.bf16.bf16.f32 "
        "{%0,%1,%2,%3}, {%4,%5,%6,%7}, {%8,%9}, {%0,%1,%2,%3};"
        : "+f"(d[0]), "+f"(d[1]), "+f"(d[2]), "+f"(d[3])
        : "r"(a[0]), "r"(a[1]), "r"(a[2]), "r"(a[3]), "r"(b[0]), "r"(b[1]));
}

__global__ __launch_bounds__(256) void gemm1_mma(const float* __restrict__ x1,
                                                 const float* __restrict__ x2) {
    __shared__ __nv_bfloat16 sA[2][128][APAD];
    __shared__ __nv_bfloat16 sB[2][128][APAD];

    const int tid  = threadIdx.x;
    const int wid  = tid >> 5;
    const int lane = tid & 31;
    const int wm   = (wid & 3) * 32;
    const int wn   = (wid >> 2) * 64;
    const int row0 = blockIdx.x * 128;

    const int gq = lane >> 2;
    const int qq = (lane & 3) * 2;

    float acc[2][8][4];
    #pragma unroll
    for (int i = 0; i < 2; i++)
        #pragma unroll
        for (int j = 0; j < 8; j++)
            #pragma unroll
            for (int q = 0; q < 4; q++) acc[i][j][q] = 0.f;

    const int ar = tid >> 1;
    const int ah = (tid & 1) * 16;
    const int gr = min(row0 + ar, NN - 1);

    float4 fa[4];
    uint4  fbh[2], fbl[2];

    auto load_chunk = [&](int ch) {
        const int k0 = ch * KC;
        const float* xr = (k0 < F1) ? (x1 + (size_t)gr * F1 + k0 + ah)
                                    : (x2 + (size_t)gr * F3 + (k0 - F1) + ah);
        #pragma unroll
        for (int v = 0; v < 4; v++)
            fa[v] = __ldg(reinterpret_cast<const float4*>(xr) + v);
        const uint4* bh = reinterpret_cast<const uint4*>(g_WhT + (size_t)ar * KTOT + k0 + ah);
        const uint4* bl = reinterpret_cast<const uint4*>(g_WlT + (size_t)ar * KTOT + k0 + ah);
        fbh[0] = bh[0]; fbh[1] = bh[1];
        fbl[0] = bl[0]; fbl[1] = bl[1];
    };

    load_chunk(0);

    for (int ch = 0; ch < NCH; ch++) {
        {
            uint32_t hw[8], lw[8];
            #pragma unroll
            for (int v = 0; v < 4; v++) {
                float4 f = fa[v];
                __nv_bfloat162 h01 = __floats2bfloat162_rn(f.x, f.y);
                __nv_bfloat162 h23 = __floats2bfloat162_rn(f.z, f.w);
                hw[v * 2 + 0] = *reinterpret_cast<uint32_t*>(&h01);
                hw[v * 2 + 1] = *reinterpret_cast<uint32_t*>(&h23);
                __nv_bfloat162 l01 = __floats2bfloat162_rn(f.x - __bfloat162float(h01.x),
                                                           f.y - __bfloat162float(h01.y));
                __nv_bfloat162 l23 = __floats2bfloat162_rn(f.z - __bfloat162float(h23.x),
                                                           f.w - __bfloat162float(h23.y));
                lw[v * 2 + 0] = *reinterpret_cast<uint32_t*>(&l01);
                lw[v * 2 + 1] = *reinterpret_cast<uint32_t*>(&l23);
            }
            *reinterpret_cast<uint4*>(&sA[0][ar][ah])     = make_uint4(hw[0], hw[1], hw[2], hw[3]);
            *reinterpret_cast<uint4*>(&sA[0][ar][ah + 8]) = make_uint4(hw[4], hw[5], hw[6], hw[7]);
            *reinterpret_cast<uint4*>(&sA[1][ar][ah])     = make_uint4(lw[0], lw[1], lw[2], lw[3]);
            *reinterpret_cast<uint4*>(&sA[1][ar][ah + 8]) = make_uint4(lw[4], lw[5], lw[6], lw[7]);
            *reinterpret_cast<uint4*>(&sB[0][ar][ah])     = fbh[0];
            *reinterpret_cast<uint4*>(&sB[0][ar][ah + 8]) = fbh[1];
            *reinterpret_cast<uint4*>(&sB[1][ar][ah])     = fbl[0];
            *reinterpret_cast<uint4*>(&sB[1][ar][ah + 8]) = fbl[1];
        }
        __syncthreads();

        if (ch + 1 < NCH) load_chunk(ch + 1);

        #pragma unroll
        for (int pass = 0; pass < 3; pass++) {
            const int ab = (pass == 1) ? 1 : 0;
            const int bb = (pass == 2) ? 1 : 0;
            #pragma unroll
            for (int ks = 0; ks < 2; ks++) {
                const int kk = ks * 16;
                uint32_t afr[2][4];
                #pragma unroll
                for (int mt = 0; mt < 2; mt++) {
                    const int mr = wm + mt * 16 + gq;
                    afr[mt][0] = *reinterpret_cast<const uint32_t*>(&sA[ab][mr    ][kk + qq]);
                    afr[mt][1] = *reinterpret_cast<const uint32_t*>(&sA[ab][mr + 8][kk + qq]);
                    afr[mt][2] = *reinterpret_cast<const uint32_t*>(&sA[ab][mr    ][kk + qq + 8]);
                    afr[mt][3] = *reinterpret_cast<const uint32_t*>(&sA[ab][mr + 8][kk + qq + 8]);
                }
                #pragma unroll
                for (int nt = 0; nt < 8; nt++) {
                    const int nr = wn + nt * 8 + gq;
                    uint32_t bfr[2];
                    bfr[0] = *reinterpret_cast<const uint32_t*>(&sB[bb][nr][kk + qq]);
                    bfr[1] = *reinterpret_cast<const uint32_t*>(&sB[bb][nr][kk + qq + 8]);
                    hmma(acc[0][nt], afr[0], bfr);
                    hmma(acc[1][nt], afr[1], bfr);
                }
            }
        }
        __syncthreads();
    }

    #pragma unroll
    for (int mt = 0; mt < 2; mt++) {
        const int r0 = row0 + wm + mt * 16 + gq;
        const int r1 = r0 + 8;
        #pragma unroll
        for (int nt = 0; nt < 8; nt++) {
            const int cc = wn + nt * 8 + qq;
            float2 bz = *reinterpret_cast<const float2*>(g_bz + cc);
            if (r0 < NN) {
                float2 v = make_float2(acc[mt][nt][0] + bz.x, acc[mt][nt][1] + bz.y);
                *reinterpret_cast<float2*>(g_z + (size_t)r0 * H + cc) = v;
            }
            if (r1 < NN) {
                float2 v = make_float2(acc[mt][nt][2] + bz.x, acc[mt][nt][3] + bz.y);
                *reinterpret_cast<float2*>(g_z + (size_t)r1 * H + cc) = v;
            }
        }
    }
}

// ============================================================
// Gather1 (pull): agg[dst] = relu(s * sum(z[src]) + t).  Warp/dst.
// ============================================================
__global__ __launch_bounds__(256) void gather1_kernel() {
    const int warp = (blockIdx.x * blockDim.x + threadIdx.x) >> 5;
    const int lane = threadIdx.x & 31;
    if (warp >= NN) return;
    const int beg = __ldg(&g_off[warp]);
    const int end = __ldg(&g_off[warp + 1]);

    float4 acc = make_float4(0.f, 0.f, 0.f, 0.f);
    for (int p = beg; p < end; p += 32) {
        const int nb = min(32, end - p);
        int eid = (p + lane < end) ? __ldg(&g_eid[p + lane]) : 0;
        for (int j = 0; j < nb; j++) {
            int src = __shfl_sync(0xffffffffu, eid, j);
            float4 v = reinterpret_cast<const float4*>(g_z + (size_t)src * H)[lane];
            acc.x += v.x; acc.y += v.y; acc.z += v.z; acc.w += v.w;
        }
    }
    float4 sv = reinterpret_cast<const float4*>(g_s)[lane];
    float4 tv = reinterpret_cast<const float4*>(g_t)[lane];
    float4 r;
    r.x = fmaxf(acc.x * sv.x + tv.x, 0.f);
    r.y = fmaxf(acc.y * sv.y + tv.y, 0.f);
    r.z = fmaxf(acc.z * sv.z + tv.z, 0.f);
    r.w = fmaxf(acc.w * sv.w + tv.w, 0.f);
    reinterpret_cast<float4*>(g_agg + (size_t)warp * H)[lane] = r;
}

// ============================================================
// GEMM2: g_z2[N,64] = agg @ Wg2   (agg already activated)
// ============================================================
__global__ __launch_bounds__(256) void gemm2_kernel(const float* __restrict__ Wg2) {
    __shared__ float As[16][64];
    __shared__ float Bs[16][64];
    const int tid = threadIdx.x;
    const int tx = tid & 15;
    const int ty = tid >> 4;
    const int row0 = blockIdx.x * 64;
    float acc[4][4] = {};

    for (int kb = 0; kb < H; kb += 16) {
        {
            int r  = tid >> 2;
            int kq = (tid & 3) << 2;
            int gr = row0 + r; if (gr >= NN) gr = NN - 1;
            float4 av = *reinterpret_cast<const float4*>(g_agg + (size_t)gr * H + kb + kq);
            As[kq + 0][r] = av.x; As[kq + 1][r] = av.y;
            As[kq + 2][r] = av.z; As[kq + 3][r] = av.w;
        }
        {
            int k  = tid >> 4;
            int c4 = (tid & 15) << 2;
            float4 bv = *reinterpret_cast<const float4*>(Wg2 + (size_t)(kb + k) * C + c4);
            *reinterpret_cast<float4*>(&Bs[k][c4]) = bv;
        }
        __syncthreads();
        #pragma unroll
        for (int k = 0; k < 16; k++) {
            float4 a = *reinterpret_cast<const float4*>(&As[k][ty * 4]);
            float4 b = *reinterpret_cast<const float4*>(&Bs[k][tx * 4]);
            float ar[4] = {a.x, a.y, a.z, a.w};
            float br[4] = {b.x, b.y, b.z, b.w};
            #pragma unroll
            for (int i = 0; i < 4; i++)
                #pragma unroll
                for (int j = 0; j < 4; j++)
                    acc[i][j] += ar[i] * br[j];
        }
        __syncthreads();
    }
    #pragma unroll
    for (int i = 0; i < 4; i++) {
        int gr = row0 + ty * 4 + i;
        if (gr < NN) {
            float4 v = make_float4(acc[i][0], acc[i][1], acc[i][2], acc[i][3]);
            *reinterpret_cast<float4*>(g_z2 + (size_t)gr * C + tx * 4) = v;
        }
    }
}

// ============================================================
// Gather2 (pull): out[dst] = bg2 + sum(z2[src]).  Warp/dst, float2/lane.
// ============================================================
__global__ __launch_bounds__(256) void gather2_kernel(const float* __restrict__ bg2,
                                                      float* __restrict__ out) {
    const int warp = (blockIdx.x * blockDim.x + threadIdx.x) >> 5;
    const int lane = threadIdx.x & 31;
    if (warp >= NN) return;
    const int beg = __ldg(&g_off[warp]);
    const int end = __ldg(&g_off[warp + 1]);

    float2 acc = make_float2(0.f, 0.f);
    for (int p = beg; p < end; p += 32) {
        const int nb = min(32, end - p);
        int eid = (p + lane < end) ? __ldg(&g_eid[p + lane]) : 0;
        for (int j = 0; j < nb; j++) {
            int src = __shfl_sync(0xffffffffu, eid, j);
            float2 v = reinterpret_cast<const float2*>(g_z2 + (size_t)src * C)[lane];
            acc.x += v.x; acc.y += v.y;
        }
    }
    float2 bb = reinterpret_cast<const float2*>(bg2)[lane];
    acc.x += bb.x; acc.y += bb.y;
    reinterpret_cast<float2*>(out + (size_t)warp * C)[lane] = acc;
}

// ============================================================
extern "C" void kernel_launch(void* const* d_in, const int* in_sizes, int n_in,
                              void* d_out, int out_size) {
    const float* x1    = (const float*)d_in[0];
    const float* x2    = (const float*)d_in[1];
    const int*   ei    = (const int*)d_in[2];
    const float* W1    = (const float*)d_in[3];
    const float* b1    = (const float*)d_in[4];
    const float* W2    = (const float*)d_in[5];
    const float* b2    = (const float*)d_in[6];
    const float* Wg1   = (const float*)d_in[7];
    const float* bg1   = (const float*)d_in[8];
    const float* Wg2   = (const float*)d_in[9];
    const float* bg2   = (const float*)d_in[10];
    const float* gamma = (const float*)d_in[11];
    const float* beta  = (const float*)d_in[12];
    const float* rmean = (const float*)d_in[13];
    const float* rvar  = (const float*)d_in[14];
    float* out = (float*)d_out;

    prep_kernel<<<KTOT + 1, H>>>(W1, b1, W2, b2, Wg1, bg1, gamma, beta, rmean, rvar);

    // ---- counting sort of edges by dst ----
    zero_cnt_kernel<<<(NN + 255) / 256, 256>>>();
    hist_kernel<<<(EE + 255) / 256, 256>>>(ei);
    scan1_kernel<<<NB1, SCAN_B>>>();
    scan2_kernel<<<1, 256>>>();
    scan3_kernel<<<NB1, SCAN_B>>>();
    fill_kernel<<<(EE + 255) / 256, 256>>>(ei);

    gemm1_mma<<<(NN + 127) / 128, 256>>>(x1, x2);

    gather1_kernel<<<(NN * 32 + 255) / 256, 256>>>();

    gemm2_kernel<<<(NN + 63) / 64, 256>>>(Wg2);

    gather2_kernel<<<(NN * 32 + 255) / 256, 256>>>(bg2, out);
}

// round 12
// speedup vs baseline: 1.9184x; 1.0624x over previous
#include <cuda_runtime.h>
#include <cuda_bf16.h>
#include <cstdint>

#define NN 100000
#define EE 1600000
#define F1 512
#define F3 128
#define KTOT 640
#define H  128
#define C  64
#define SW 0.2f
#define FW 0.8f
#define BN_EPS 1e-5f

#define SCAN_B 512
#define NB1 ((NN + SCAN_B - 1) / SCAN_B)   // 196

// ---- scratch (device globals) ----
__device__ __nv_bfloat16 g_WhT[H * KTOT];
__device__ __nv_bfloat16 g_WlT[H * KTOT];
__device__ float g_bz[H];
__device__ float g_s[H];
__device__ float g_t[H];
__device__ float g_z[(size_t)NN * H];
__device__ float g_agg[(size_t)NN * H];
__device__ float g_z2[(size_t)NN * C];
__device__ int   g_cnt[NN];
__device__ int   g_off[NN + 1];
__device__ int   g_eid[EE];
__device__ int   g_bsum[NB1];

// ============================================================
// Prolog: combined weights -> bf16 hi/lo (transposed) + BN affine.
// ============================================================
__global__ void prep_kernel(const float* __restrict__ W1, const float* __restrict__ b1,
                            const float* __restrict__ W2, const float* __restrict__ b2,
                            const float* __restrict__ Wg1, const float* __restrict__ bg1,
                            const float* __restrict__ gamma, const float* __restrict__ beta,
                            const float* __restrict__ rmean, const float* __restrict__ rvar) {
    int j = threadIdx.x;
    int b = blockIdx.x;
    __shared__ float a[H];
    if (b < KTOT) {
        float scale = (b < F1) ? FW : SW;
        a[j] = (b < F1) ? W1[b * H + j] : W2[(b - F1) * H + j];
        __syncthreads();
        float acc = 0.f;
        #pragma unroll 8
        for (int k = 0; k < H; k++) acc += a[k] * Wg1[k * H + j];
        acc *= scale;
        __nv_bfloat16 hi = __float2bfloat16(acc);
        __nv_bfloat16 lo = __float2bfloat16(acc - __bfloat162float(hi));
        g_WhT[j * KTOT + b] = hi;
        g_WlT[j * KTOT + b] = lo;
    } else {
        a[j] = FW * b1[j] + SW * b2[j];
        __syncthreads();
        float acc = 0.f;
        #pragma unroll 8
        for (int k = 0; k < H; k++) acc += a[k] * Wg1[k * H + j];
        g_bz[j] = acc;
        float sc = gamma[j] * rsqrtf(rvar[j] + BN_EPS);
        g_s[j] = sc;
        g_t[j] = (bg1[j] - rmean[j]) * sc + beta[j];
    }
}

// ============================================================
// Counting sort of edges by dst.
// ============================================================
__global__ void zero_cnt_kernel() {
    int i = blockIdx.x * blockDim.x + threadIdx.x;
    if (i < NN) g_cnt[i] = 0;
}

__global__ void hist_kernel(const int* __restrict__ ei) {
    int e = blockIdx.x * blockDim.x + threadIdx.x;
    if (e >= EE) return;
    atomicAdd(&g_cnt[__ldg(ei + EE + e)], 1);
}

__global__ __launch_bounds__(SCAN_B) void scan1_kernel() {
    __shared__ int s[SCAN_B];
    int tid = threadIdx.x;
    int i = blockIdx.x * SCAN_B + tid;
    int v = (i < NN) ? g_cnt[i] : 0;
    s[tid] = v;
    __syncthreads();
    #pragma unroll
    for (int d = 1; d < SCAN_B; d <<= 1) {
        int t = (tid >= d) ? s[tid - d] : 0;
        __syncthreads();
        s[tid] += t;
        __syncthreads();
    }
    if (i < NN) g_off[i] = s[tid] - v;
    if (tid == SCAN_B - 1) g_bsum[blockIdx.x] = s[tid];
}

__global__ __launch_bounds__(256) void scan2_kernel() {
    __shared__ int s[256];
    int tid = threadIdx.x;
    int v = (tid < NB1) ? g_bsum[tid] : 0;
    s[tid] = v;
    __syncthreads();
    #pragma unroll
    for (int d = 1; d < 256; d <<= 1) {
        int t = (tid >= d) ? s[tid - d] : 0;
        __syncthreads();
        s[tid] += t;
        __syncthreads();
    }
    if (tid < NB1) g_bsum[tid] = s[tid] - v;
}

__global__ __launch_bounds__(SCAN_B) void scan3_kernel() {
    int i = blockIdx.x * SCAN_B + threadIdx.x;
    if (i < NN) {
        int o = g_off[i] + g_bsum[blockIdx.x];
        g_off[i] = o;
        g_cnt[i] = o;
    }
    if (i == 0) g_off[NN] = EE;
}

__global__ void fill_kernel(const int* __restrict__ ei) {
    int e = blockIdx.x * blockDim.x + threadIdx.x;
    if (e >= EE) return;
    int src = __ldg(ei + e);
    int dst = __ldg(ei + EE + e);
    int pos = atomicAdd(&g_cnt[dst], 1);
    g_eid[pos] = src;
}

// ============================================================
// GEMM1 (HMMA): z = x @ Wh + x_hi @ Wl + bz
// Double-buffered SMEM: one __syncthreads per chunk, staging
// of chunk ch+1 overlaps HMMA of chunk ch.
// ============================================================
#define KC    32
#define APAD  40
#define NCH   (KTOT / KC)
#define SM_HALF (2 * 128 * APAD)                 // elems per hi/lo pair buffer set
#define SM_G1TOT (4 * 128 * APAD * 2 * 2)        // bytes: (A+B) x 2 bufs x hi/lo

__device__ __forceinline__ void hmma(float* d, const uint32_t* a, const uint32_t* b) {
    asm volatile(
        "mma.sync.aligned.m16n8k16.row.col.f32.bf16.bf16.f32 "
        "{%0,%1,%2,%3}, {%4,%5,%6,%7}, {%8,%9}, {%0,%1,%2,%3};"
        : "+f"(d[0]), "+f"(d[1]), "+f"(d[2]), "+f"(d[3])
        : "r"(a[0]), "r"(a[1]), "r"(a[2]), "r"(a[3]), "r"(b[0]), "r"(b[1]));
}

__global__ __launch_bounds__(256) void gemm1_mma(const float* __restrict__ x1,
                                                 const float* __restrict__ x2) {
    extern __shared__ __nv_bfloat16 sm[];
    // layout: sA[buf][hl][128][APAD], sB[buf][hl][128][APAD]
    __nv_bfloat16* sAp = sm;                       // 2*2*128*APAD
    __nv_bfloat16* sBp = sm + 2 * SM_HALF;
    #define SA(buf, hl, r, k) sAp[(((buf) * 2 + (hl)) * 128 + (r)) * APAD + (k)]
    #define SB(buf, hl, r, k) sBp[(((buf) * 2 + (hl)) * 128 + (r)) * APAD + (k)]

    const int tid  = threadIdx.x;
    const int wid  = tid >> 5;
    const int lane = tid & 31;
    const int wm   = (wid & 3) * 32;
    const int wn   = (wid >> 2) * 64;
    const int row0 = blockIdx.x * 128;

    const int gq = lane >> 2;
    const int qq = (lane & 3) * 2;

    float acc[2][8][4];
    #pragma unroll
    for (int i = 0; i < 2; i++)
        #pragma unroll
        for (int j = 0; j < 8; j++)
            #pragma unroll
            for (int q = 0; q < 4; q++) acc[i][j][q] = 0.f;

    const int ar = tid >> 1;
    const int ah = (tid & 1) * 16;
    const int gr = min(row0 + ar, NN - 1);

    float4 fa[4];
    uint4  fbh[2], fbl[2];

    auto load_chunk = [&](int ch) {
        const int k0 = ch * KC;
        const float* xr = (k0 < F1) ? (x1 + (size_t)gr * F1 + k0 + ah)
                                    : (x2 + (size_t)gr * F3 + (k0 - F1) + ah);
        #pragma unroll
        for (int v = 0; v < 4; v++)
            fa[v] = __ldg(reinterpret_cast<const float4*>(xr) + v);
        const uint4* bh = reinterpret_cast<const uint4*>(g_WhT + (size_t)ar * KTOT + k0 + ah);
        const uint4* bl = reinterpret_cast<const uint4*>(g_WlT + (size_t)ar * KTOT + k0 + ah);
        fbh[0] = bh[0]; fbh[1] = bh[1];
        fbl[0] = bl[0]; fbl[1] = bl[1];
    };

    auto stage = [&](int buf) {
        uint32_t hw[8], lw[8];
        #pragma unroll
        for (int v = 0; v < 4; v++) {
            float4 f = fa[v];
            __nv_bfloat162 h01 = __floats2bfloat162_rn(f.x, f.y);
            __nv_bfloat162 h23 = __floats2bfloat162_rn(f.z, f.w);
            hw[v * 2 + 0] = *reinterpret_cast<uint32_t*>(&h01);
            hw[v * 2 + 1] = *reinterpret_cast<uint32_t*>(&h23);
            __nv_bfloat162 l01 = __floats2bfloat162_rn(f.x - __bfloat162float(h01.x),
                                                       f.y - __bfloat162float(h01.y));
            __nv_bfloat162 l23 = __floats2bfloat162_rn(f.z - __bfloat162float(h23.x),
                                                       f.w - __bfloat162float(h23.y));
            lw[v * 2 + 0] = *reinterpret_cast<uint32_t*>(&l01);
            lw[v * 2 + 1] = *reinterpret_cast<uint32_t*>(&l23);
        }
        *reinterpret_cast<uint4*>(&SA(buf, 0, ar, ah))     = make_uint4(hw[0], hw[1], hw[2], hw[3]);
        *reinterpret_cast<uint4*>(&SA(buf, 0, ar, ah + 8)) = make_uint4(hw[4], hw[5], hw[6], hw[7]);
        *reinterpret_cast<uint4*>(&SA(buf, 1, ar, ah))     = make_uint4(lw[0], lw[1], lw[2], lw[3]);
        *reinterpret_cast<uint4*>(&SA(buf, 1, ar, ah + 8)) = make_uint4(lw[4], lw[5], lw[6], lw[7]);
        *reinterpret_cast<uint4*>(&SB(buf, 0, ar, ah))     = fbh[0];
        *reinterpret_cast<uint4*>(&SB(buf, 0, ar, ah + 8)) = fbh[1];
        *reinterpret_cast<uint4*>(&SB(buf, 1, ar, ah))     = fbl[0];
        *reinterpret_cast<uint4*>(&SB(buf, 1, ar, ah + 8)) = fbl[1];
    };

    load_chunk(0);
    stage(0);
    load_chunk(1);

    for (int ch = 0; ch < NCH; ch++) {
        const int cur = ch & 1;
        __syncthreads();   // buffer `cur` staged by all warps; prior compute on `cur^1` done

        // stage next chunk into the other buffer (overlaps compute below)
        if (ch + 1 < NCH) {
            stage(cur ^ 1);
            if (ch + 2 < NCH) load_chunk(ch + 2);
        }

        #pragma unroll
        for (int pass = 0; pass < 3; pass++) {
            const int ab = (pass == 1) ? 1 : 0;
            const int bb = (pass == 2) ? 1 : 0;
            #pragma unroll
            for (int ks = 0; ks < 2; ks++) {
                const int kk = ks * 16;
                uint32_t afr[2][4];
                #pragma unroll
                for (int mt = 0; mt < 2; mt++) {
                    const int mr = wm + mt * 16 + gq;
                    afr[mt][0] = *reinterpret_cast<const uint32_t*>(&SA(cur, ab, mr,     kk + qq));
                    afr[mt][1] = *reinterpret_cast<const uint32_t*>(&SA(cur, ab, mr + 8, kk + qq));
                    afr[mt][2] = *reinterpret_cast<const uint32_t*>(&SA(cur, ab, mr,     kk + qq + 8));
                    afr[mt][3] = *reinterpret_cast<const uint32_t*>(&SA(cur, ab, mr + 8, kk + qq + 8));
                }
                #pragma unroll
                for (int nt = 0; nt < 8; nt++) {
                    const int nr = wn + nt * 8 + gq;
                    uint32_t bfr[2];
                    bfr[0] = *reinterpret_cast<const uint32_t*>(&SB(cur, bb, nr, kk + qq));
                    bfr[1] = *reinterpret_cast<const uint32_t*>(&SB(cur, bb, nr, kk + qq + 8));
                    hmma(acc[0][nt], afr[0], bfr);
                    hmma(acc[1][nt], afr[1], bfr);
                }
            }
        }
    }

    #pragma unroll
    for (int mt = 0; mt < 2; mt++) {
        const int r0 = row0 + wm + mt * 16 + gq;
        const int r1 = r0 + 8;
        #pragma unroll
        for (int nt = 0; nt < 8; nt++) {
            const int cc = wn + nt * 8 + qq;
            float2 bz = *reinterpret_cast<const float2*>(g_bz + cc);
            if (r0 < NN) {
                float2 v = make_float2(acc[mt][nt][0] + bz.x, acc[mt][nt][1] + bz.y);
                *reinterpret_cast<float2*>(g_z + (size_t)r0 * H + cc) = v;
            }
            if (r1 < NN) {
                float2 v = make_float2(acc[mt][nt][2] + bz.x, acc[mt][nt][3] + bz.y);
                *reinterpret_cast<float2*>(g_z + (size_t)r1 * H + cc) = v;
            }
        }
    }
}

// ============================================================
// Gather1 (pull): agg[dst] = relu(s * sum(z[src]) + t).  Warp/dst.
// ============================================================
__global__ __launch_bounds__(256) void gather1_kernel() {
    const int warp = (blockIdx.x * blockDim.x + threadIdx.x) >> 5;
    const int lane = threadIdx.x & 31;
    if (warp >= NN) return;
    const int beg = __ldg(&g_off[warp]);
    const int end = __ldg(&g_off[warp + 1]);

    float4 acc = make_float4(0.f, 0.f, 0.f, 0.f);
    for (int p = beg; p < end; p += 32) {
        const int nb = min(32, end - p);
        int eid = (p + lane < end) ? __ldg(&g_eid[p + lane]) : 0;
        for (int j = 0; j < nb; j++) {
            int src = __shfl_sync(0xffffffffu, eid, j);
            float4 v = reinterpret_cast<const float4*>(g_z + (size_t)src * H)[lane];
            acc.x += v.x; acc.y += v.y; acc.z += v.z; acc.w += v.w;
        }
    }
    float4 sv = reinterpret_cast<const float4*>(g_s)[lane];
    float4 tv = reinterpret_cast<const float4*>(g_t)[lane];
    float4 r;
    r.x = fmaxf(acc.x * sv.x + tv.x, 0.f);
    r.y = fmaxf(acc.y * sv.y + tv.y, 0.f);
    r.z = fmaxf(acc.z * sv.z + tv.z, 0.f);
    r.w = fmaxf(acc.w * sv.w + tv.w, 0.f);
    reinterpret_cast<float4*>(g_agg + (size_t)warp * H)[lane] = r;
}

// ============================================================
// GEMM2: g_z2[N,64] = agg @ Wg2
// ============================================================
__global__ __launch_bounds__(256) void gemm2_kernel(const float* __restrict__ Wg2) {
    __shared__ float As[16][64];
    __shared__ float Bs[16][64];
    const int tid = threadIdx.x;
    const int tx = tid & 15;
    const int ty = tid >> 4;
    const int row0 = blockIdx.x * 64;
    float acc[4][4] = {};

    for (int kb = 0; kb < H; kb += 16) {
        {
            int r  = tid >> 2;
            int kq = (tid & 3) << 2;
            int gr = row0 + r; if (gr >= NN) gr = NN - 1;
            float4 av = *reinterpret_cast<const float4*>(g_agg + (size_t)gr * H + kb + kq);
            As[kq + 0][r] = av.x; As[kq + 1][r] = av.y;
            As[kq + 2][r] = av.z; As[kq + 3][r] = av.w;
        }
        {
            int k  = tid >> 4;
            int c4 = (tid & 15) << 2;
            float4 bv = *reinterpret_cast<const float4*>(Wg2 + (size_t)(kb + k) * C + c4);
            *reinterpret_cast<float4*>(&Bs[k][c4]) = bv;
        }
        __syncthreads();
        #pragma unroll
        for (int k = 0; k < 16; k++) {
            float4 a = *reinterpret_cast<const float4*>(&As[k][ty * 4]);
            float4 b = *reinterpret_cast<const float4*>(&Bs[k][tx * 4]);
            float ar[4] = {a.x, a.y, a.z, a.w};
            float br[4] = {b.x, b.y, b.z, b.w};
            #pragma unroll
            for (int i = 0; i < 4; i++)
                #pragma unroll
                for (int j = 0; j < 4; j++)
                    acc[i][j] += ar[i] * br[j];
        }
        __syncthreads();
    }
    #pragma unroll
    for (int i = 0; i < 4; i++) {
        int gr = row0 + ty * 4 + i;
        if (gr < NN) {
            float4 v = make_float4(acc[i][0], acc[i][1], acc[i][2], acc[i][3]);
            *reinterpret_cast<float4*>(g_z2 + (size_t)gr * C + tx * 4) = v;
        }
    }
}

// ============================================================
// Gather2 (pull): out[dst] = bg2 + sum(z2[src]).  Warp/dst.
// ============================================================
__global__ __launch_bounds__(256) void gather2_kernel(const float* __restrict__ bg2,
                                                      float* __restrict__ out) {
    const int warp = (blockIdx.x * blockDim.x + threadIdx.x) >> 5;
    const int lane = threadIdx.x & 31;
    if (warp >= NN) return;
    const int beg = __ldg(&g_off[warp]);
    const int end = __ldg(&g_off[warp + 1]);

    float2 acc = make_float2(0.f, 0.f);
    for (int p = beg; p < end; p += 32) {
        const int nb = min(32, end - p);
        int eid = (p + lane < end) ? __ldg(&g_eid[p + lane]) : 0;
        for (int j = 0; j < nb; j++) {
            int src = __shfl_sync(0xffffffffu, eid, j);
            float2 v = reinterpret_cast<const float2*>(g_z2 + (size_t)src * C)[lane];
            acc.x += v.x; acc.y += v.y;
        }
    }
    float2 bb = reinterpret_cast<const float2*>(bg2)[lane];
    acc.x += bb.x; acc.y += bb.y;
    reinterpret_cast<float2*>(out + (size_t)warp * C)[lane] = acc;
}

// ============================================================
extern "C" void kernel_launch(void* const* d_in, const int* in_sizes, int n_in,
                              void* d_out, int out_size) {
    const float* x1    = (const float*)d_in[0];
    const float* x2    = (const float*)d_in[1];
    const int*   ei    = (const int*)d_in[2];
    const float* W1    = (const float*)d_in[3];
    const float* b1    = (const float*)d_in[4];
    const float* W2    = (const float*)d_in[5];
    const float* b2    = (const float*)d_in[6];
    const float* Wg1   = (const float*)d_in[7];
    const float* bg1   = (const float*)d_in[8];
    const float* Wg2   = (const float*)d_in[9];
    const float* bg2   = (const float*)d_in[10];
    const float* gamma = (const float*)d_in[11];
    const float* beta  = (const float*)d_in[12];
    const float* rmean = (const float*)d_in[13];
    const float* rvar  = (const float*)d_in[14];
    float* out = (float*)d_out;

    // one-time infra (host objects only; no device memory)
    static cudaStream_t sSort = nullptr;
    static cudaEvent_t evFork = nullptr, evJoin = nullptr;
    if (sSort == nullptr) {
        cudaStreamCreate(&sSort);
        cudaEventCreateWithFlags(&evFork, cudaEventDisableTiming);
        cudaEventCreateWithFlags(&evJoin, cudaEventDisableTiming);
    }
    cudaFuncSetAttribute(gemm1_mma, cudaFuncAttributeMaxDynamicSharedMemorySize, SM_G1TOT);

    // ---- fork: counting sort on side stream, dense work on main ----
    cudaEventRecord(evFork, 0);
    cudaStreamWaitEvent(sSort, evFork, 0);

    zero_cnt_kernel<<<(NN + 255) / 256, 256, 0, sSort>>>();
    hist_kernel<<<(EE + 255) / 256, 256, 0, sSort>>>(ei);
    scan1_kernel<<<NB1, SCAN_B, 0, sSort>>>();
    scan2_kernel<<<1, 256, 0, sSort>>>();
    scan3_kernel<<<NB1, SCAN_B, 0, sSort>>>();
    fill_kernel<<<(EE + 255) / 256, 256, 0, sSort>>>(ei);
    cudaEventRecord(evJoin, sSort);

    prep_kernel<<<KTOT + 1, H>>>(W1, b1, W2, b2, Wg1, bg1, gamma, beta, rmean, rvar);
    gemm1_mma<<<(NN + 127) / 128, 256, SM_G1TOT>>>(x1, x2);

    // ---- join: gathers need the sorted CSR ----
    cudaStreamWaitEvent(0, evJoin, 0);

    gather1_kernel<<<(NN * 32 + 255) / 256, 256>>>();
    gemm2_kernel<<<(NN + 63) / 64, 256>>>(Wg2);
    gather2_kernel<<<(NN * 32 + 255) / 256, 256>>>(bg2, out);
}